// round 1
// baseline (speedup 1.0000x reference)
#include <cuda_runtime.h>
#include <math.h>

#define BB 16
#define N_IN 6250
#define N_OUTC 25000
#define CCH 64
#define SS 9
#define NNZ 75000

// ---------------- device scratch (static, allowed) ----------------
__device__ float g_pooled[(size_t)BB * N_OUTC * CCH];   // [B][N_OUT][64]
__device__ int   g_cnt[N_OUTC];
__device__ int   g_fill[N_OUTC];
__device__ int   g_start[N_OUTC + 1];
__device__ int   g_csr_col[NNZ];
__device__ float g_csr_val[NNZ];

// ---------------- CSR build ----------------
__global__ void k_zero_cnt() {
    int i = blockIdx.x * blockDim.x + threadIdx.x;
    if (i < N_OUTC) { g_cnt[i] = 0; g_fill[i] = 0; }
}

__global__ void k_count(const int* __restrict__ row) {
    int i = blockIdx.x * blockDim.x + threadIdx.x;
    if (i < NNZ) atomicAdd(&g_cnt[row[i]], 1);
}

// single-block exclusive scan over 25000 counts
__global__ void k_scan() {
    __shared__ int sh[1024];
    __shared__ int carry;
    int tid = threadIdx.x;
    if (tid == 0) carry = 0;
    __syncthreads();
    const int NT = (N_OUTC + 1023) / 1024;
    for (int t = 0; t < NT; ++t) {
        int i = t * 1024 + tid;
        int v = (i < N_OUTC) ? g_cnt[i] : 0;
        sh[tid] = v;
        __syncthreads();
        for (int off = 1; off < 1024; off <<= 1) {
            int add = (tid >= off) ? sh[tid - off] : 0;
            __syncthreads();
            sh[tid] += add;
            __syncthreads();
        }
        if (i < N_OUTC) g_start[i] = carry + sh[tid] - v;
        int total = sh[1023];
        __syncthreads();
        if (tid == 0) carry += total;
        __syncthreads();
    }
    if (tid == 0) g_start[N_OUTC] = carry;
}

__global__ void k_fill(const float* __restrict__ vals,
                       const int* __restrict__ row,
                       const int* __restrict__ col) {
    int i = blockIdx.x * blockDim.x + threadIdx.x;
    if (i < NNZ) {
        int r = row[i];
        int pos = g_start[r] + atomicAdd(&g_fill[r], 1);
        g_csr_col[pos] = col[i];
        g_csr_val[pos] = vals[i];
    }
}

// ---------------- atomic-free pooling: pooled[b][r][c] = sum_j val_j * x[b][col_j][c]
__global__ void k_pool(const float* __restrict__ x) {
    int b = blockIdx.y;
    int r = blockIdx.x * 4 + (threadIdx.x >> 6);
    int c = threadIdx.x & 63;
    if (r >= N_OUTC) return;
    int s0 = g_start[r], s1 = g_start[r + 1];
    const float* xb = x + (size_t)b * N_IN * CCH;
    float acc = 0.f;
    for (int j = s0; j < s1; ++j)
        acc += g_csr_val[j] * xb[(size_t)g_csr_col[j] * CCH + c];
    g_pooled[((size_t)b * N_OUTC + r) * CCH + c] = acc;
}

// ---------------- spiral gather + GEMM (M=B*N_OUT, K=576, N=64) + bias + ELU
// Block: 256 threads, tile 128(M) x 64(N); thread micro-tile 8x4.
__global__ __launch_bounds__(256) void k_gemm(const int* __restrict__ sp,
                                              const float* __restrict__ W,
                                              const float* __restrict__ bias,
                                              float* __restrict__ out) {
    __shared__ float As[128 * 64];   // [row][kk]
    __shared__ float Bs[64 * 64];    // [kk][co]
    __shared__ int   spw[128 * 9];

    const int b   = blockIdx.y;
    const int n0  = blockIdx.x * 128;
    const int tid = threadIdx.x;
    const int tx  = tid & 15;   // 16 col groups (4 cols each)
    const int ty  = tid >> 4;   // 16 row groups (8 rows each)

    // load spiral indices for this block's rows (clamp invalid rows to 0)
    for (int i = tid; i < 128 * 9; i += 256) {
        int r = n0 + i / 9;
        spw[i] = (r < N_OUTC) ? sp[(size_t)r * 9 + (i % 9)] : 0;
    }

    float acc[8][4];
#pragma unroll
    for (int i = 0; i < 8; ++i)
#pragma unroll
        for (int j = 0; j < 4; ++j) acc[i][j] = 0.f;

    const float* poolb = g_pooled + (size_t)b * N_OUTC * CCH;

    for (int s = 0; s < SS; ++s) {
        __syncthreads();
        // A tile: 128 gathered pooled rows, each 64 contiguous floats
#pragma unroll
        for (int p = 0; p < 8; ++p) {
            int lin = p * 256 + tid;
            int row = lin >> 4, f4 = lin & 15;
            int g = spw[row * 9 + s];
            reinterpret_cast<float4*>(As)[lin] =
                reinterpret_cast<const float4*>(poolb + (size_t)g * CCH)[f4];
        }
        // B tile: W rows s*64 .. s*64+63 (contiguous 16KB)
        const float* Wс = W + (size_t)(s * 64) * 64;
#pragma unroll
        for (int p = 0; p < 4; ++p) {
            int lin = p * 256 + tid;
            reinterpret_cast<float4*>(Bs)[lin] =
                reinterpret_cast<const float4*>(Wс)[lin];
        }
        __syncthreads();

        // rank-4 updates: per 4-k group: 4 + 8 LDS.128, 128 FFMA per thread
#pragma unroll
        for (int kg = 0; kg < 16; ++kg) {
            float4 bv0 = reinterpret_cast<const float4*>(Bs)[(kg * 4 + 0) * 16 + tx];
            float4 bv1 = reinterpret_cast<const float4*>(Bs)[(kg * 4 + 1) * 16 + tx];
            float4 bv2 = reinterpret_cast<const float4*>(Bs)[(kg * 4 + 2) * 16 + tx];
            float4 bv3 = reinterpret_cast<const float4*>(Bs)[(kg * 4 + 3) * 16 + tx];
#pragma unroll
            for (int i = 0; i < 8; ++i) {
                float4 av = reinterpret_cast<const float4*>(As)[(ty * 8 + i) * 16 + kg];
                acc[i][0] += av.x * bv0.x; acc[i][1] += av.x * bv0.y;
                acc[i][2] += av.x * bv0.z; acc[i][3] += av.x * bv0.w;
                acc[i][0] += av.y * bv1.x; acc[i][1] += av.y * bv1.y;
                acc[i][2] += av.y * bv1.z; acc[i][3] += av.y * bv1.w;
                acc[i][0] += av.z * bv2.x; acc[i][1] += av.z * bv2.y;
                acc[i][2] += av.z * bv2.z; acc[i][3] += av.z * bv2.w;
                acc[i][0] += av.w * bv3.x; acc[i][1] += av.w * bv3.y;
                acc[i][2] += av.w * bv3.z; acc[i][3] += av.w * bv3.w;
            }
        }
    }

    // epilogue: bias + ELU, vectorized store
    float4 bb = reinterpret_cast<const float4*>(bias)[tx];
#pragma unroll
    for (int i = 0; i < 8; ++i) {
        int r = n0 + ty * 8 + i;
        if (r < N_OUTC) {
            float4 v;
            v.x = acc[i][0] + bb.x;
            v.y = acc[i][1] + bb.y;
            v.z = acc[i][2] + bb.z;
            v.w = acc[i][3] + bb.w;
            v.x = v.x > 0.f ? v.x : expm1f(v.x);
            v.y = v.y > 0.f ? v.y : expm1f(v.y);
            v.z = v.z > 0.f ? v.z : expm1f(v.z);
            v.w = v.w > 0.f ? v.w : expm1f(v.w);
            reinterpret_cast<float4*>(out)[((size_t)b * N_OUTC + r) * 16 + tx] = v;
        }
    }
}

// ---------------- launcher ----------------
extern "C" void kernel_launch(void* const* d_in, const int* in_sizes, int n_in,
                              void* d_out, int out_size) {
    const float* x    = (const float*)d_in[0];
    const float* tval = (const float*)d_in[1];
    const int*   trow = (const int*)d_in[2];
    const int*   tcol = (const int*)d_in[3];
    const int*   sp   = (const int*)d_in[4];
    const float* W    = (const float*)d_in[5];
    const float* bias = (const float*)d_in[6];
    float* out = (float*)d_out;

    k_zero_cnt<<<(N_OUTC + 255) / 256, 256>>>();
    k_count<<<(NNZ + 255) / 256, 256>>>(trow);
    k_scan<<<1, 1024>>>();
    k_fill<<<(NNZ + 255) / 256, 256>>>(tval, trow, tcol);

    dim3 pg((N_OUTC + 3) / 4, BB);
    k_pool<<<pg, 256>>>(x);

    dim3 gg((N_OUTC + 127) / 128, BB);
    k_gemm<<<gg, 256>>>(sp, W, bias, out);
}

// round 3
// speedup vs baseline: 1.5148x; 1.5148x over previous
#include <cuda_runtime.h>
#include <cuda_bf16.h>
#include <math.h>
#include <stdint.h>

#define BB 16
#define N_IN 6250
#define N_OUTC 25000
#define CCH 64
#define SS 9
#define NNZ 75000

// ---------------- device scratch ----------------
__device__ uint32_t g_pool[(size_t)BB * N_OUTC * CCH];   // packed hi<<16 | lo (bf16 split)
__device__ int   g_cnt[N_OUTC];
__device__ int   g_fillc[N_OUTC];
__device__ int   g_start[N_OUTC + 1];
__device__ int   g_csr_col[NNZ];
__device__ float g_csr_val[NNZ];
// per-slot 64(k)x64(n) bf16 tiles, XOR-swizzled [k][n] layout
__device__ __align__(16) unsigned char g_Bhi[SS * 8192];
__device__ __align__(16) unsigned char g_Blo[SS * 8192];

__device__ __forceinline__ uint32_t smem_u32(const void* p) {
    uint32_t a;
    asm("{ .reg .u64 t; cvta.to.shared.u64 t, %1; cvt.u32.u64 %0, t; }" : "=r"(a) : "l"(p));
    return a;
}
__device__ __forceinline__ uint32_t swz(uint32_t off) { return off ^ ((off >> 3) & 0x70); }

#define LDSM_X4(r0, r1, r2, r3, a) \
    asm volatile("ldmatrix.sync.aligned.m8n8.x4.shared.b16 {%0,%1,%2,%3}, [%4];" \
                 : "=r"(r0), "=r"(r1), "=r"(r2), "=r"(r3) : "r"(a))
#define LDSM_X4T(r0, r1, r2, r3, a) \
    asm volatile("ldmatrix.sync.aligned.m8n8.x4.trans.shared.b16 {%0,%1,%2,%3}, [%4];" \
                 : "=r"(r0), "=r"(r1), "=r"(r2), "=r"(r3) : "r"(a))

__device__ __forceinline__ void mma_bf16(float* d, const uint32_t* a, uint32_t b0, uint32_t b1) {
    asm volatile(
        "mma.sync.aligned.m16n8k16.row.col.f32.bf16.bf16.f32 "
        "{%0,%1,%2,%3}, {%4,%5,%6,%7}, {%8,%9}, {%0,%1,%2,%3};"
        : "+f"(d[0]), "+f"(d[1]), "+f"(d[2]), "+f"(d[3])
        : "r"(a[0]), "r"(a[1]), "r"(a[2]), "r"(a[3]), "r"(b0), "r"(b1));
}

// ---------------- CSR build ----------------
__global__ void k_zero_cnt() {
    int i = blockIdx.x * blockDim.x + threadIdx.x;
    if (i < N_OUTC) { g_cnt[i] = 0; g_fillc[i] = 0; }
}
__global__ void k_count(const int* __restrict__ row) {
    int i = blockIdx.x * blockDim.x + threadIdx.x;
    if (i < NNZ) atomicAdd(&g_cnt[row[i]], 1);
}
__global__ void k_scan() {
    __shared__ int sh[1024];
    __shared__ int carry;
    int tid = threadIdx.x;
    if (tid == 0) carry = 0;
    __syncthreads();
    const int NT = (N_OUTC + 1023) / 1024;
    for (int t = 0; t < NT; ++t) {
        int i = t * 1024 + tid;
        int v = (i < N_OUTC) ? g_cnt[i] : 0;
        sh[tid] = v;
        __syncthreads();
        for (int off = 1; off < 1024; off <<= 1) {
            int add = (tid >= off) ? sh[tid - off] : 0;
            __syncthreads();
            sh[tid] += add;
            __syncthreads();
        }
        if (i < N_OUTC) g_start[i] = carry + sh[tid] - v;
        int total = sh[1023];
        __syncthreads();
        if (tid == 0) carry += total;
        __syncthreads();
    }
    if (tid == 0) g_start[N_OUTC] = carry;
}
__global__ void k_fill(const float* __restrict__ vals,
                       const int* __restrict__ row,
                       const int* __restrict__ col) {
    int i = blockIdx.x * blockDim.x + threadIdx.x;
    if (i < NNZ) {
        int r = row[i];
        int pos = g_start[r] + atomicAdd(&g_fillc[r], 1);
        g_csr_col[pos] = col[i];
        g_csr_val[pos] = vals[i];
    }
}

// ---------------- W prep: [k][n] bf16 hi/lo, XOR-swizzled ----------------
__global__ void k_prepW(const float* __restrict__ W) {
    int i = blockIdx.x * blockDim.x + threadIdx.x;
    if (i >= SS * 64 * 64) return;
    int s = i / 4096, rem = i % 4096;
    int kk = rem / 64, n = rem % 64;
    float w = W[(size_t)(s * 64 + kk) * 64 + n];
    __nv_bfloat16 h = __float2bfloat16(w);
    float hf = __bfloat162float(h);
    __nv_bfloat16 l = __float2bfloat16(w - hf);
    uint32_t boff = (uint32_t)kk * 128 + (uint32_t)n * 2;
    uint32_t sw = swz(boff);
    *reinterpret_cast<__nv_bfloat16*>(g_Bhi + (size_t)s * 8192 + sw) = h;
    *reinterpret_cast<__nv_bfloat16*>(g_Blo + (size_t)s * 8192 + sw) = l;
}

// ---------------- pooling -> packed bf16 hi/lo ----------------
__global__ void k_pool(const float* __restrict__ x) {
    int b = blockIdx.y;
    int r = blockIdx.x * 4 + (threadIdx.x >> 6);
    int c = threadIdx.x & 63;
    if (r >= N_OUTC) return;
    int s0 = g_start[r], s1 = g_start[r + 1];
    const float* xb = x + (size_t)b * N_IN * CCH;
    float acc = 0.f;
    for (int j = s0; j < s1; ++j)
        acc += g_csr_val[j] * xb[(size_t)g_csr_col[j] * CCH + c];
    __nv_bfloat16 h = __float2bfloat16(acc);
    float hf = __bfloat162float(h);
    __nv_bfloat16 l = __float2bfloat16(acc - hf);
    g_pool[((size_t)b * N_OUTC + r) * CCH + c] =
        ((uint32_t)__bfloat16_as_ushort(h) << 16) | (uint32_t)__bfloat16_as_ushort(l);
}

// ---------------- HMMA GEMM: tile 128(M)x64(N), K=9x64, split-bf16 3-product ----------------
#define SM_SPW   0          // 128*9*4 = 4608
#define SM_AHI   5120       // 128x64 bf16 = 16384
#define SM_ALO   21504
#define SM_BHI   37888      // 64x64 bf16 = 8192
#define SM_BLO   46080
#define SM_BYTES 54272
#define SM_ALLOC (SM_BYTES + 1024)

__global__ __launch_bounds__(256, 2) void k_gemm(const int* __restrict__ sp,
                                                 const float* __restrict__ bias,
                                                 float* __restrict__ out) {
    extern __shared__ unsigned char smem_raw[];
    uint32_t raw = smem_u32(smem_raw);
    uint32_t sbase = (raw + 1023u) & ~1023u;
    unsigned char* smem = smem_raw + (sbase - raw);

    const int tid  = threadIdx.x;
    const int wid  = tid >> 5;
    const int lane = tid & 31;
    const int bidx = blockIdx.y;
    const int n0   = blockIdx.x * 128;

    const int wm = wid & 3;        // M warp tile (32 rows each)
    const int wn = wid >> 2;       // N warp tile (32 cols each)
    const int q  = lane >> 3;      // ldmatrix quadrant
    const int lr = lane & 7;
    const int gid = lane >> 2;
    const int tig = lane & 3;

    // stage spiral indices
    int* spw = reinterpret_cast<int*>(smem + SM_SPW);
    for (int i = tid; i < 128 * SS; i += 256) {
        int r = n0 + i / SS;
        spw[i] = (r < N_OUTC) ? sp[(size_t)r * SS + (i % SS)] : 0;
    }

    float acc[2][4][4];
#pragma unroll
    for (int a = 0; a < 2; ++a)
#pragma unroll
        for (int b = 0; b < 4; ++b)
#pragma unroll
            for (int c = 0; c < 4; ++c) acc[a][b][c] = 0.f;

    const uint32_t* poolb = g_pool + (size_t)bidx * N_OUTC * CCH;

    // per-lane ldmatrix address pieces (offsets, swizzled later)
    const int arow_base = wm * 32 + (q & 1) * 8 + lr;  // + mt*16
    const int achunk    = (q >> 1) * 16;               // +kk*32 bytes
    const int bkrow     = (q & 1) * 8 + lr;            // + kk*16
    const int bcol_base = (wn * 32 + (q >> 1) * 8) * 2; // + t*32 bytes

    __syncthreads();

    for (int s = 0; s < SS; ++s) {
        // ---- gather A rows (16 lanes per 256B packed row), unpack hi/lo into swizzled tiles
#pragma unroll
        for (int it = 0; it < 8; ++it) {
            int idx = it * 256 + tid;
            int r = idx >> 4, c4 = idx & 15;
            int g = spw[r * SS + s];
            uint4 p = reinterpret_cast<const uint4*>(poolb + (size_t)g * CCH)[c4];
            uint32_t hw0 = (p.y & 0xFFFF0000u) | (p.x >> 16);
            uint32_t hw1 = (p.w & 0xFFFF0000u) | (p.z >> 16);
            uint32_t lw0 = (p.y << 16) | (p.x & 0xFFFFu);
            uint32_t lw1 = (p.w << 16) | (p.z & 0xFFFFu);
            uint32_t sz = swz((uint32_t)(r * 128 + c4 * 8));
            *reinterpret_cast<uint2*>(smem + SM_AHI + sz) = make_uint2(hw0, hw1);
            *reinterpret_cast<uint2*>(smem + SM_ALO + sz) = make_uint2(lw0, lw1);
        }
        // ---- B tiles: copy pre-swizzled 8KB hi + 8KB lo
        {
            const float4* srch = reinterpret_cast<const float4*>(g_Bhi + (size_t)s * 8192);
            const float4* srcl = reinterpret_cast<const float4*>(g_Blo + (size_t)s * 8192);
            float4* dsth = reinterpret_cast<float4*>(smem + SM_BHI);
            float4* dstl = reinterpret_cast<float4*>(smem + SM_BLO);
#pragma unroll
            for (int p2 = 0; p2 < 2; ++p2) {
                dsth[p2 * 256 + tid] = srch[p2 * 256 + tid];
                dstl[p2 * 256 + tid] = srcl[p2 * 256 + tid];
            }
        }
        __syncthreads();

        // ---- fragments + 3-product MMA
#pragma unroll
        for (int kk = 0; kk < 4; ++kk) {
            uint32_t ah[2][4], al[2][4], bh[2][4], bl[2][4];
#pragma unroll
            for (int mt = 0; mt < 2; ++mt) {
                uint32_t off = (uint32_t)((arow_base + mt * 16) * 128 + kk * 32 + achunk);
                uint32_t a1 = sbase + SM_AHI + swz(off);
                uint32_t a2 = sbase + SM_ALO + swz(off);
                LDSM_X4(ah[mt][0], ah[mt][1], ah[mt][2], ah[mt][3], a1);
                LDSM_X4(al[mt][0], al[mt][1], al[mt][2], al[mt][3], a2);
            }
#pragma unroll
            for (int t = 0; t < 2; ++t) {
                uint32_t off = (uint32_t)((kk * 16 + bkrow) * 128 + bcol_base + t * 32);
                uint32_t b1 = sbase + SM_BHI + swz(off);
                uint32_t b2 = sbase + SM_BLO + swz(off);
                LDSM_X4T(bh[t][0], bh[t][1], bh[t][2], bh[t][3], b1);
                LDSM_X4T(bl[t][0], bl[t][1], bl[t][2], bl[t][3], b2);
            }
#pragma unroll
            for (int mt = 0; mt < 2; ++mt)
#pragma unroll
                for (int ni = 0; ni < 4; ++ni) {
                    uint32_t bh0 = bh[ni >> 1][(ni & 1) * 2 + 0];
                    uint32_t bh1 = bh[ni >> 1][(ni & 1) * 2 + 1];
                    uint32_t bl0 = bl[ni >> 1][(ni & 1) * 2 + 0];
                    uint32_t bl1 = bl[ni >> 1][(ni & 1) * 2 + 1];
                    mma_bf16(acc[mt][ni], ah[mt], bh0, bh1);
                    mma_bf16(acc[mt][ni], ah[mt], bl0, bl1);
                    mma_bf16(acc[mt][ni], al[mt], bh0, bh1);
                }
        }
        __syncthreads();
    }

    // ---- epilogue: bias + ELU, float2 stores
#pragma unroll
    for (int mt = 0; mt < 2; ++mt) {
#pragma unroll
        for (int half = 0; half < 2; ++half) {
            int r = n0 + wm * 32 + mt * 16 + gid + half * 8;
            if (r < N_OUTC) {
                float* orow = out + ((size_t)bidx * N_OUTC + r) * 64;
#pragma unroll
                for (int ni = 0; ni < 4; ++ni) {
                    int col = wn * 32 + ni * 8 + tig * 2;
                    float2 bb = *reinterpret_cast<const float2*>(bias + col);
                    float vx = acc[mt][ni][half * 2 + 0] + bb.x;
                    float vy = acc[mt][ni][half * 2 + 1] + bb.y;
                    vx = vx > 0.f ? vx : expm1f(vx);
                    vy = vy > 0.f ? vy : expm1f(vy);
                    *reinterpret_cast<float2*>(orow + col) = make_float2(vx, vy);
                }
            }
        }
    }
}

// ---------------- launcher ----------------
extern "C" void kernel_launch(void* const* d_in, const int* in_sizes, int n_in,
                              void* d_out, int out_size) {
    const float* x    = (const float*)d_in[0];
    const float* tval = (const float*)d_in[1];
    const int*   trow = (const int*)d_in[2];
    const int*   tcol = (const int*)d_in[3];
    const int*   sp   = (const int*)d_in[4];
    const float* W    = (const float*)d_in[5];
    const float* bias = (const float*)d_in[6];
    float* out = (float*)d_out;

    cudaFuncSetAttribute(k_gemm, cudaFuncAttributeMaxDynamicSharedMemorySize, SM_ALLOC);

    k_zero_cnt<<<(N_OUTC + 255) / 256, 256>>>();
    k_count<<<(NNZ + 255) / 256, 256>>>(trow);
    k_scan<<<1, 1024>>>();
    k_fill<<<(NNZ + 255) / 256, 256>>>(tval, trow, tcol);
    k_prepW<<<(SS * 64 * 64 + 255) / 256, 256>>>(W);

    dim3 pg((N_OUTC + 3) / 4, BB);
    k_pool<<<pg, 256>>>(x);

    dim3 gg((N_OUTC + 127) / 128, BB);
    k_gemm<<<gg, 256, SM_ALLOC>>>(sp, bias, out);
}

// round 6
// speedup vs baseline: 2.3873x; 1.5760x over previous
#include <cuda_runtime.h>
#include <cuda_bf16.h>
#include <math.h>
#include <stdint.h>

#define BB 16
#define N_IN 6250
#define N_OUTC 25000
#define CCH 64
#define SS 9
#define NNZ 75000

// ---------------- device scratch ----------------
__device__ __align__(16) __nv_bfloat16 g_phi[(size_t)BB * N_OUTC * CCH]; // pooled hi plane
__device__ __align__(16) __nv_bfloat16 g_plo[(size_t)BB * N_OUTC * CCH]; // pooled lo plane
__device__ int   g_cnt[N_OUTC];
__device__ int   g_fillc[N_OUTC];
__device__ int   g_start[N_OUTC + 1];
__device__ int   g_csr_col[NNZ];
__device__ float g_csr_val[NNZ];
// per-slot 64(k)x64(n) bf16 tiles, XOR-swizzled [k][n] layout
__device__ __align__(16) unsigned char g_Bhi[SS * 8192];
__device__ __align__(16) unsigned char g_Blo[SS * 8192];

__device__ __forceinline__ uint32_t smem_u32(const void* p) {
    uint32_t a;
    asm("{ .reg .u64 t; cvta.to.shared.u64 t, %1; cvt.u32.u64 %0, t; }" : "=r"(a) : "l"(p));
    return a;
}
__device__ __forceinline__ uint32_t swz(uint32_t off) { return off ^ ((off >> 3) & 0x70); }

__device__ __forceinline__ void cp16(uint32_t dst, const void* src) {
    asm volatile("cp.async.cg.shared.global [%0], [%1], 16;" :: "r"(dst), "l"(src));
}
#define CP_COMMIT() asm volatile("cp.async.commit_group;" ::: "memory")
#define CP_WAIT1()  asm volatile("cp.async.wait_group 1;" ::: "memory")

#define LDSM_X4(r0, r1, r2, r3, a) \
    asm volatile("ldmatrix.sync.aligned.m8n8.x4.shared.b16 {%0,%1,%2,%3}, [%4];" \
                 : "=r"(r0), "=r"(r1), "=r"(r2), "=r"(r3) : "r"(a))
#define LDSM_X4T(r0, r1, r2, r3, a) \
    asm volatile("ldmatrix.sync.aligned.m8n8.x4.trans.shared.b16 {%0,%1,%2,%3}, [%4];" \
                 : "=r"(r0), "=r"(r1), "=r"(r2), "=r"(r3) : "r"(a))

__device__ __forceinline__ void mma_bf16(float* d, const uint32_t* a, uint32_t b0, uint32_t b1) {
    asm volatile(
        "mma.sync.aligned.m16n8k16.row.col.f32.bf16.bf16.f32 "
        "{%0,%1,%2,%3}, {%4,%5,%6,%7}, {%8,%9}, {%0,%1,%2,%3};"
        : "+f"(d[0]), "+f"(d[1]), "+f"(d[2]), "+f"(d[3])
        : "r"(a[0]), "r"(a[1]), "r"(a[2]), "r"(a[3]), "r"(b0), "r"(b1));
}

// ---------------- CSR build ----------------
__global__ void k_zero_cnt() {
    int i = blockIdx.x * blockDim.x + threadIdx.x;
    if (i < N_OUTC) { g_cnt[i] = 0; g_fillc[i] = 0; }
}
__global__ void k_count(const int* __restrict__ row) {
    int i = blockIdx.x * blockDim.x + threadIdx.x;
    if (i < NNZ) atomicAdd(&g_cnt[row[i]], 1);
}
// 1024-thread shfl-based scan over 25000 counts
__global__ void k_scan() {
    __shared__ int wsum[32];
    __shared__ int carry;
    int tid = threadIdx.x, lane = tid & 31, w = tid >> 5;
    if (tid == 0) carry = 0;
    __syncthreads();
    const int NT = (N_OUTC + 1023) / 1024;
    for (int t = 0; t < NT; ++t) {
        int i = t * 1024 + tid;
        int v = (i < N_OUTC) ? g_cnt[i] : 0;
        int sc = v;
#pragma unroll
        for (int o = 1; o < 32; o <<= 1) {
            int u = __shfl_up_sync(0xFFFFFFFFu, sc, o);
            if (lane >= o) sc += u;
        }
        if (lane == 31) wsum[w] = sc;
        __syncthreads();
        if (w == 0) {
            int ws = wsum[lane];
#pragma unroll
            for (int o = 1; o < 32; o <<= 1) {
                int u = __shfl_up_sync(0xFFFFFFFFu, ws, o);
                if (lane >= o) ws += u;
            }
            wsum[lane] = ws;
        }
        __syncthreads();
        int excl = sc - v + (w > 0 ? wsum[w - 1] : 0) + carry;
        if (i < N_OUTC) g_start[i] = excl;
        __syncthreads();
        if (tid == 1023) carry = excl + v;
        __syncthreads();
    }
    if (tid == 0) g_start[N_OUTC] = carry;
}
__global__ void k_fill(const float* __restrict__ vals,
                       const int* __restrict__ row,
                       const int* __restrict__ col) {
    int i = blockIdx.x * blockDim.x + threadIdx.x;
    if (i < NNZ) {
        int r = row[i];
        int pos = g_start[r] + atomicAdd(&g_fillc[r], 1);
        g_csr_col[pos] = col[i];
        g_csr_val[pos] = vals[i];
    }
}

// ---------------- W prep: [k][n] bf16 hi/lo, XOR-swizzled ----------------
__global__ void k_prepW(const float* __restrict__ W) {
    int i = blockIdx.x * blockDim.x + threadIdx.x;
    if (i >= SS * 64 * 64) return;
    int s = i / 4096, rem = i % 4096;
    int kk = rem / 64, n = rem % 64;
    float w = W[(size_t)(s * 64 + kk) * 64 + n];
    __nv_bfloat16 h = __float2bfloat16(w);
    float hf = __bfloat162float(h);
    __nv_bfloat16 l = __float2bfloat16(w - hf);
    uint32_t sw = swz((uint32_t)kk * 128 + (uint32_t)n * 2);
    *reinterpret_cast<__nv_bfloat16*>(g_Bhi + (size_t)s * 8192 + sw) = h;
    *reinterpret_cast<__nv_bfloat16*>(g_Blo + (size_t)s * 8192 + sw) = l;
}

// ---------------- pooling -> separate bf16 hi/lo planes ----------------
__global__ void k_pool(const float* __restrict__ x) {
    int b = blockIdx.y;
    int r = blockIdx.x * 4 + (threadIdx.x >> 6);
    int c = threadIdx.x & 63;
    if (r >= N_OUTC) return;
    int s0 = g_start[r], s1 = g_start[r + 1];
    const float* xb = x + (size_t)b * N_IN * CCH;
    float acc = 0.f;
    for (int j = s0; j < s1; ++j)
        acc += g_csr_val[j] * xb[(size_t)g_csr_col[j] * CCH + c];
    __nv_bfloat16 h = __float2bfloat16(acc);
    float hf = __bfloat162float(h);
    __nv_bfloat16 l = __float2bfloat16(acc - hf);
    size_t o = ((size_t)b * N_OUTC + r) * CCH + c;
    g_phi[o] = h;
    g_plo[o] = l;
}

// ---------------- HMMA GEMM: 2-stage cp.async pipeline over 9 slots ----------------
#define SM_SPW     0            // 128*9*4 = 4608
#define SM_STAGE0  5120
#define ST_AHI     0            // 16384
#define ST_ALO     16384        // 16384
#define ST_BHI     32768        // 8192
#define ST_BLO     40960        // 8192
#define ST_BYTES   49152
#define SM_ALLOC   (SM_STAGE0 + 2 * ST_BYTES + 1024)

__global__ __launch_bounds__(256, 2) void k_gemm(const int* __restrict__ sp,
                                                 const float* __restrict__ bias,
                                                 float* __restrict__ out) {
    extern __shared__ unsigned char smem_raw[];
    uint32_t raw = smem_u32(smem_raw);
    uint32_t sbase = (raw + 1023u) & ~1023u;
    unsigned char* smem = smem_raw + (sbase - raw);

    const int tid  = threadIdx.x;
    const int wid  = tid >> 5;
    const int lane = tid & 31;
    const int bidx = blockIdx.y;
    const int n0   = blockIdx.x * 128;

    const int wm = wid & 3;
    const int wn = wid >> 2;
    const int q  = lane >> 3;
    const int lr = lane & 7;
    const int gid = lane >> 2;
    const int tig = lane & 3;

    // stage spiral indices
    int* spw = reinterpret_cast<int*>(smem + SM_SPW);
    for (int i = tid; i < 128 * SS; i += 256) {
        int r = n0 + i / SS;
        spw[i] = (r < N_OUTC) ? sp[(size_t)r * SS + (i % SS)] : 0;
    }
    __syncthreads();

    const __nv_bfloat16* phib = g_phi + (size_t)bidx * N_OUTC * CCH;
    const __nv_bfloat16* plob = g_plo + (size_t)bidx * N_OUTC * CCH;

    // per-thread gather coords: 8 threads per 128B row
    const int grow = tid >> 3;      // +256/8=32 per it
    const int gch  = tid & 7;

    // issue loads for slot s into stage buffer
    auto load_stage = [&](int s, int buf) {
        uint32_t stg = sbase + SM_STAGE0 + buf * ST_BYTES;
#pragma unroll
        for (int it = 0; it < 4; ++it) {
            int row = it * 32 + grow;
            int g = spw[row * SS + s];
            uint32_t d = swz((uint32_t)(row * 128 + gch * 16));
            cp16(stg + ST_AHI + d, phib + (size_t)g * CCH + gch * 8);
            cp16(stg + ST_ALO + d, plob + (size_t)g * CCH + gch * 8);
        }
#pragma unroll
        for (int it = 0; it < 2; ++it) {
            uint32_t o = (uint32_t)(it * 256 + tid) * 16;
            cp16(stg + ST_BHI + o, g_Bhi + (size_t)s * 8192 + o);
            cp16(stg + ST_BLO + o, g_Blo + (size_t)s * 8192 + o);
        }
    };

    float acc[2][4][4];
#pragma unroll
    for (int a = 0; a < 2; ++a)
#pragma unroll
        for (int b = 0; b < 4; ++b)
#pragma unroll
            for (int c = 0; c < 4; ++c) acc[a][b][c] = 0.f;

    const int arow_base = wm * 32 + (q & 1) * 8 + lr;
    const int achunk    = (q >> 1) * 16;
    const int bkrow     = (q & 1) * 8 + lr;
    const int bcol_base = (wn * 32 + (q >> 1) * 8) * 2;

    load_stage(0, 0); CP_COMMIT();
    load_stage(1, 1); CP_COMMIT();

    for (int s = 0; s < SS; ++s) {
        CP_WAIT1();
        __syncthreads();

        uint32_t stg = sbase + SM_STAGE0 + (s & 1) * ST_BYTES;
#pragma unroll
        for (int kk = 0; kk < 4; ++kk) {
            uint32_t ah[2][4], al[2][4], bh[2][4], bl[2][4];
#pragma unroll
            for (int mt = 0; mt < 2; ++mt) {
                uint32_t off = swz((uint32_t)((arow_base + mt * 16) * 128 + kk * 32 + achunk));
                LDSM_X4(ah[mt][0], ah[mt][1], ah[mt][2], ah[mt][3], stg + ST_AHI + off);
                LDSM_X4(al[mt][0], al[mt][1], al[mt][2], al[mt][3], stg + ST_ALO + off);
            }
#pragma unroll
            for (int t = 0; t < 2; ++t) {
                uint32_t off = swz((uint32_t)((kk * 16 + bkrow) * 128 + bcol_base + t * 32));
                LDSM_X4T(bh[t][0], bh[t][1], bh[t][2], bh[t][3], stg + ST_BHI + off);
                LDSM_X4T(bl[t][0], bl[t][1], bl[t][2], bl[t][3], stg + ST_BLO + off);
            }
#pragma unroll
            for (int mt = 0; mt < 2; ++mt)
#pragma unroll
                for (int ni = 0; ni < 4; ++ni) {
                    uint32_t bh0 = bh[ni >> 1][(ni & 1) * 2 + 0];
                    uint32_t bh1 = bh[ni >> 1][(ni & 1) * 2 + 1];
                    uint32_t bl0 = bl[ni >> 1][(ni & 1) * 2 + 0];
                    uint32_t bl1 = bl[ni >> 1][(ni & 1) * 2 + 1];
                    mma_bf16(acc[mt][ni], ah[mt], bh0, bh1);
                    mma_bf16(acc[mt][ni], ah[mt], bl0, bl1);
                    mma_bf16(acc[mt][ni], al[mt], bh0, bh1);
                }
        }
        __syncthreads();
        if (s + 2 < SS) load_stage(s + 2, s & 1);
        CP_COMMIT();
    }

    // ---- epilogue: bias + ELU
#pragma unroll
    for (int mt = 0; mt < 2; ++mt) {
#pragma unroll
        for (int half = 0; half < 2; ++half) {
            int r = n0 + wm * 32 + mt * 16 + gid + half * 8;
            if (r < N_OUTC) {
                float* orow = out + ((size_t)bidx * N_OUTC + r) * 64;
#pragma unroll
                for (int ni = 0; ni < 4; ++ni) {
                    int col = wn * 32 + ni * 8 + tig * 2;
                    float2 bb = *reinterpret_cast<const float2*>(bias + col);
                    float vx = acc[mt][ni][half * 2 + 0] + bb.x;
                    float vy = acc[mt][ni][half * 2 + 1] + bb.y;
                    vx = vx > 0.f ? vx : expm1f(vx);
                    vy = vy > 0.f ? vy : expm1f(vy);
                    *reinterpret_cast<float2*>(orow + col) = make_float2(vx, vy);
                }
            }
        }
    }
}

// ---------------- launcher ----------------
extern "C" void kernel_launch(void* const* d_in, const int* in_sizes, int n_in,
                              void* d_out, int out_size) {
    const float* x    = (const float*)d_in[0];
    const float* tval = (const float*)d_in[1];
    const int*   trow = (const int*)d_in[2];
    const int*   tcol = (const int*)d_in[3];
    const int*   sp   = (const int*)d_in[4];
    const float* W    = (const float*)d_in[5];
    const float* bias = (const float*)d_in[6];
    float* out = (float*)d_out;

    cudaFuncSetAttribute(k_gemm, cudaFuncAttributeMaxDynamicSharedMemorySize, SM_ALLOC);

    k_zero_cnt<<<(N_OUTC + 255) / 256, 256>>>();
    k_count<<<(NNZ + 255) / 256, 256>>>(trow);
    k_scan<<<1, 1024>>>();
    k_fill<<<(NNZ + 255) / 256, 256>>>(tval, trow, tcol);
    k_prepW<<<(SS * 64 * 64 + 255) / 256, 256>>>(W);

    dim3 pg((N_OUTC + 3) / 4, BB);
    k_pool<<<pg, 256>>>(x);

    dim3 gg((N_OUTC + 127) / 128, BB);
    k_gemm<<<gg, 256, SM_ALLOC>>>(sp, bias, out);
}